// round 10
// baseline (speedup 1.0000x reference)
#include <cuda_runtime.h>
#include <cuda_bf16.h>
#include <cstdint>

// Problem constants
#define B    256
#define T    256
#define NQ   1000
#define DK   128
#define DV   128
#define CC   32
#define TOUT 255
#define NROWS (B * TOUT)         // 65280

typedef unsigned long long u64;

// ---------------- packed f32x2 helpers (sm_103a) --------------------------
__device__ __forceinline__ u64 pack2(float lo, float hi) {
    u64 r; asm("mov.b64 %0, {%1, %2};" : "=l"(r) : "f"(lo), "f"(hi)); return r;
}
__device__ __forceinline__ void unpack2(u64 v, float& lo, float& hi) {
    asm("mov.b64 {%0, %1}, %2;" : "=f"(lo), "=f"(hi) : "l"(v));
}
__device__ __forceinline__ u64 fma2(u64 a, u64 b, u64 c) {
    u64 d; asm("fma.rn.f32x2 %0, %1, %2, %3;" : "=l"(d) : "l"(a), "l"(b), "l"(c)); return d;
}

// ---------------- device scratch ------------------------------------------
__device__ __align__(16) float  g_wt[NQ * CC];        // softmax(k_emb @ Mk)
__device__ __align__(16) float  g_g [NQ * DK];        // k_emb @ f_W[128:] + f_b
__device__ __align__(16) float2 g_ea[2 * NQ * DV];    // (-sigmoid(vW_e), tanh(vW_a))
__device__ __align__(16) float  g_rt[NROWS * DV];     // rt scratch
__device__ __align__(16) u64    g_fw2[(DK / 2) * DK]; // f_W rows 0..127, i-pair packed

// ---------------- precompute kernel 1: EA + WT only (scan dependencies) ----
#define EA_BLOCKS 125
#define WT_BLOCKS 125
#define PRE_BLOCKS (EA_BLOCKS + WT_BLOCKS)

__global__ void __launch_bounds__(256)
pre_fused_kernel(const float* __restrict__ k_emb,
                 const float* __restrict__ v_emb,
                 const float* __restrict__ Mk,
                 const float* __restrict__ e_W,
                 const float* __restrict__ e_b,
                 const float* __restrict__ a_W,
                 const float* __restrict__ a_b) {
    __shared__ __align__(16) float sbuf[16 * DK];
    int bid = blockIdx.x;
    int tid = threadIdx.x;

    if (bid < EA_BLOCKS) {
        // ---- pre_ea: (-e, a) for 16 rows ----
        int row0 = bid * 16;
        int j  = tid & 127;
        int rh = tid >> 7;
        #pragma unroll
        for (int u = 0; u < 2; u++) {
            int idx = tid + u * 256;
            reinterpret_cast<float4*>(sbuf)[idx] =
                __ldg(reinterpret_cast<const float4*>(v_emb + row0 * DV) + idx);
        }
        __syncthreads();

        float acce[8], acca[8];
        float eb = __ldg(e_b + j), ab = __ldg(a_b + j);
        #pragma unroll
        for (int r = 0; r < 8; r++) { acce[r] = eb; acca[r] = ab; }

        const float* xb = sbuf + rh * 8 * DV;
        #pragma unroll 4
        for (int k = 0; k < DV; k += 4) {
            float we0 = __ldg(e_W + (k + 0) * DV + j);
            float we1 = __ldg(e_W + (k + 1) * DV + j);
            float we2 = __ldg(e_W + (k + 2) * DV + j);
            float we3 = __ldg(e_W + (k + 3) * DV + j);
            float wa0 = __ldg(a_W + (k + 0) * DV + j);
            float wa1 = __ldg(a_W + (k + 1) * DV + j);
            float wa2 = __ldg(a_W + (k + 2) * DV + j);
            float wa3 = __ldg(a_W + (k + 3) * DV + j);
            #pragma unroll
            for (int r = 0; r < 8; r++) {
                float4 xv = *reinterpret_cast<const float4*>(xb + r * DV + k);
                acce[r] = fmaf(xv.x, we0, acce[r]);
                acce[r] = fmaf(xv.y, we1, acce[r]);
                acce[r] = fmaf(xv.z, we2, acce[r]);
                acce[r] = fmaf(xv.w, we3, acce[r]);
                acca[r] = fmaf(xv.x, wa0, acca[r]);
                acca[r] = fmaf(xv.y, wa1, acca[r]);
                acca[r] = fmaf(xv.z, wa2, acca[r]);
                acca[r] = fmaf(xv.w, wa3, acca[r]);
            }
        }
        #pragma unroll
        for (int r = 0; r < 8; r++) {
            int gr = row0 + rh * 8 + r;
            g_ea[gr * DV + j] = make_float2(-1.0f / (1.0f + expf(-acce[r])),
                                            tanhf(acca[r]));
        }
    } else {
        // ---- pre_wt: softmax(k_emb @ Mk), one q per warp ----
        int warp = tid >> 5;
        int lane = tid & 31;
        int q = (bid - EA_BLOCKS) * 8 + warp;
        const float* krow = k_emb + q * DK;
        float acc = 0.f;
        #pragma unroll 8
        for (int k = 0; k < DK; k++)
            acc = fmaf(__ldg(krow + k), __ldg(Mk + k * CC + lane), acc);
        float mx = acc;
        #pragma unroll
        for (int off = 16; off; off >>= 1)
            mx = fmaxf(mx, __shfl_xor_sync(0xffffffffu, mx, off));
        float e = expf(acc - mx);
        float s = e;
        #pragma unroll
        for (int off = 16; off; off >>= 1)
            s += __shfl_xor_sync(0xffffffffu, s, off);
        g_wt[q * CC + lane] = e / s;
    }
}

// ---------------- scan kernel: scan blocks + PG/PK side roles --------------
// bids [0,128): sequential scan (2 batches/block, 2 d-cols/thread, unroll-8).
// bids [128,191): pre_g (g_g GEMM, 16 rows each) -- consumed by readout only.
// bids [191,223): pre_pack (g_fw2)               -- consumed by readout only.
// Side-role blocks co-schedule with scan blocks (reg/smem budgets fit 2/SM)
// and finish long before the scan does.
#define SC_BLOCKS  128
#define PG2_BLOCKS 63
#define PK2_BLOCKS 32
#define SCAN_GRID  (SC_BLOCKS + PG2_BLOCKS + PK2_BLOCKS)

__device__ __forceinline__ void scan_loadW(int s, u64 W2[16]) {
    const ulonglong2* wp = reinterpret_cast<const ulonglong2*>(g_wt + s * CC);
    #pragma unroll
    for (int u = 0; u < 8; u++) {
        ulonglong2 v = __ldg(wp + u);
        W2[2 * u]     = v.x;
        W2[2 * u + 1] = v.y;
    }
}

__device__ __forceinline__ float scan_step(u64 m2[16], const u64 W2[16],
                                           float ne, float a) {
    u64 en2 = pack2(ne, ne);
    u64 a2  = pack2(a, a);
    u64 acc0 = 0ull, acc1 = 0ull;
    #pragma unroll
    for (int p = 0; p < 16; p++) {
        u64 mo = m2[p];
        if (p & 1) acc1 = fma2(W2[p], mo, acc1);
        else       acc0 = fma2(W2[p], mo, acc0);
        u64 tmp = fma2(mo, en2, a2);          // a - e*m
        m2[p] = fma2(W2[p], tmp, mo);         // m + w*(a - e*m)
    }
    float x0, x1, y0, y1;
    unpack2(acc0, x0, x1);
    unpack2(acc1, y0, y1);
    return (x0 + x1) + (y0 + y1);
}

__global__ void __launch_bounds__(128)
scan_kernel(const int* __restrict__ skills,
            const int* __restrict__ responses,
            const float* __restrict__ Mv0,
            const float* __restrict__ k_emb,
            const float* __restrict__ f_W,
            const float* __restrict__ f_b) {
    __shared__ __align__(16) float sbuf[16 * DK];   // used by PG role only
    int tid = threadIdx.x;

    if (blockIdx.x >= SC_BLOCKS) {
        int role = blockIdx.x - SC_BLOCKS;
        if (role < PG2_BLOCKS) {
            // ---- pre_g: g = k_emb @ f_W[128:] + f_b, 16 rows, 128 thr ----
            int row0 = role * 16;
            int j = tid;
            #pragma unroll
            for (int u = 0; u < 4; u++) {
                int idx = tid + u * 128;              // 512 float4 total
                int r   = idx >> 5;
                int gr  = row0 + r; if (gr >= NQ) gr = NQ - 1;
                reinterpret_cast<float4*>(sbuf)[idx] =
                    __ldg(reinterpret_cast<const float4*>(k_emb + gr * DK) + (idx & 31));
            }
            __syncthreads();

            float acc[16];
            float fb = __ldg(f_b + j);
            #pragma unroll
            for (int r = 0; r < 16; r++) acc[r] = fb;

            #pragma unroll 2
            for (int k = 0; k < DK; k += 4) {
                float w0 = __ldg(f_W + (DK + k + 0) * DK + j);
                float w1 = __ldg(f_W + (DK + k + 1) * DK + j);
                float w2 = __ldg(f_W + (DK + k + 2) * DK + j);
                float w3 = __ldg(f_W + (DK + k + 3) * DK + j);
                #pragma unroll
                for (int r = 0; r < 16; r++) {
                    float4 xv = *reinterpret_cast<const float4*>(sbuf + r * DK + k);
                    acc[r] = fmaf(xv.x, w0, acc[r]);
                    acc[r] = fmaf(xv.y, w1, acc[r]);
                    acc[r] = fmaf(xv.z, w2, acc[r]);
                    acc[r] = fmaf(xv.w, w3, acc[r]);
                }
            }
            #pragma unroll
            for (int r = 0; r < 16; r++) {
                int gr = row0 + r;
                if (gr < NQ) g_g[gr * DK + j] = acc[r];
            }
        } else {
            // ---- pre_pack: f_W lower half -> u64 i-pairs (256/block) ----
            int base = (role - PG2_BLOCKS) * 256;
            #pragma unroll
            for (int u = 0; u < 2; u++) {
                int idx = base + tid + u * 128;
                int ip = idx >> 7;
                int j  = idx & 127;
                g_fw2[idx] = pack2(__ldg(f_W + (2 * ip) * DK + j),
                                   __ldg(f_W + (2 * ip + 1) * DK + j));
            }
        }
        return;
    }

    // ---------------- scan role (round-9 core, unchanged) ----------------
    int half = tid >> 6;
    int td   = tid & 63;
    int b    = blockIdx.x * 2 + half;
    int d0   = td;
    int d1   = td + 64;

    u64 m0[16], m1[16];
    #pragma unroll
    for (int p = 0; p < 16; p++) {
        m0[p] = pack2(__ldg(Mv0 + (2 * p) * DV + d0),
                      __ldg(Mv0 + (2 * p + 1) * DV + d0));
        m1[p] = pack2(__ldg(Mv0 + (2 * p) * DV + d1),
                      __ldg(Mv0 + (2 * p + 1) * DV + d1));
    }

    const int* srow = skills + b * T;
    const int* rrow = responses + b * T;
    float* rtp0 = g_rt + (b * TOUT) * DV + d0;
    float* rtp1 = g_rt + (b * TOUT) * DV + d1;

    int    sE[8];
    float2 E0[8], E1[8];
    #pragma unroll
    for (int k = 0; k < 8; k++) {
        int s = __ldg(srow + k);
        int q = s + NQ * __ldg(rrow + k);
        sE[k] = s;
        E0[k] = __ldg(g_ea + q * DV + d0);
        E1[k] = __ldg(g_ea + q * DV + d1);
    }
    int sCur = __ldg(srow + 8);
    int qCur = sCur + NQ * __ldg(rrow + 8);

    u64 WA[16], WB[16];
    scan_loadW(sE[0], WA);

#define SCAN_BODY_STEP(k, Wc, Wn)                                          \
    {                                                                      \
        scan_loadW(sE[((k) + 1) & 7], Wn);                                 \
        rtp0[(t + (k)) * DV] = scan_step(m0, Wc, E0[k].x, E0[k].y);        \
        rtp1[(t + (k)) * DV] = scan_step(m1, Wc, E1[k].x, E1[k].y);        \
        E0[k] = __ldg(g_ea + qCur * DV + d0);                              \
        E1[k] = __ldg(g_ea + qCur * DV + d1);                              \
        sE[k] = sCur;                                                      \
        int ni = t + 9 + (k); if (ni > T - 1) ni = T - 1;                  \
        sCur = __ldg(srow + ni);                                           \
        qCur = sCur + NQ * __ldg(rrow + ni);                               \
    }

    for (int t = 0; t < 248; t += 8) {
        SCAN_BODY_STEP(0, WA, WB)
        SCAN_BODY_STEP(1, WB, WA)
        SCAN_BODY_STEP(2, WA, WB)
        SCAN_BODY_STEP(3, WB, WA)
        SCAN_BODY_STEP(4, WA, WB)
        SCAN_BODY_STEP(5, WB, WA)
        SCAN_BODY_STEP(6, WA, WB)
        SCAN_BODY_STEP(7, WB, WA)
    }
#undef SCAN_BODY_STEP

    {
        const int t = 248;
#define SCAN_TAIL_STEP(k, Wc, Wn)                                          \
        {                                                                  \
            scan_loadW(sE[(k) + 1], Wn);                                   \
            rtp0[(t + (k)) * DV] = scan_step(m0, Wc, E0[k].x, E0[k].y);    \
            rtp1[(t + (k)) * DV] = scan_step(m1, Wc, E1[k].x, E1[k].y);    \
        }
        SCAN_TAIL_STEP(0, WA, WB)
        SCAN_TAIL_STEP(1, WB, WA)
        SCAN_TAIL_STEP(2, WA, WB)
        SCAN_TAIL_STEP(3, WB, WA)
        SCAN_TAIL_STEP(4, WA, WB)
        SCAN_TAIL_STEP(5, WB, WA)
        rtp0[254 * DV] = scan_step(m0, WA, E0[6].x, E0[6].y);
        rtp1[254 * DV] = scan_step(m1, WA, E1[6].x, E1[6].y);
#undef SCAN_TAIL_STEP
    }
}

// ---------------- readout: GEMM + tanh + dot(p_W) + sigmoid ---------------
#define RT_ROWS 64
__global__ void __launch_bounds__(256)
readout_kernel(const float* __restrict__ p_W,
               const float* __restrict__ p_b,
               const int* __restrict__ skills,
               const int* __restrict__ responses,
               float* __restrict__ out,
               float* __restrict__ out2) {
    __shared__ __align__(16) float xs[RT_ROWS * DK];

    int tid  = threadIdx.x;
    int jg   = tid & 31;
    int rg   = tid >> 5;          // warp id 0..7
    int j0   = jg * 4;
    int row0 = blockIdx.x * RT_ROWS;

    {
        const float4* src = reinterpret_cast<const float4*>(g_rt + row0 * DK);
        float4* dst = reinterpret_cast<float4*>(xs);
        #pragma unroll
        for (int u = 0; u < (RT_ROWS * DK / 4) / 256; u++)
            dst[tid + u * 256] = src[tid + u * 256];
    }

    u64 acc2[8][4];
    #pragma unroll
    for (int r = 0; r < 8; r++) {
        int gr = row0 + rg * 8 + r;
        int bb = gr / TOUT;
        int tt = gr - bb * TOUT;
        int sk = __ldg(skills + bb * T + tt);
        float4 g = __ldg(reinterpret_cast<const float4*>(g_g + sk * DK + j0));
        acc2[r][0] = pack2(g.x, 0.f);
        acc2[r][1] = pack2(g.y, 0.f);
        acc2[r][2] = pack2(g.z, 0.f);
        acc2[r][3] = pack2(g.w, 0.f);
    }
    __syncthreads();

    const float* xb = xs + rg * 8 * DK;

    #pragma unroll 4
    for (int ip = 0; ip < DK / 2; ip++) {
        const ulonglong2* wp =
            reinterpret_cast<const ulonglong2*>(g_fw2 + ip * DK + j0);
        ulonglong2 wv0 = __ldg(wp);
        ulonglong2 wv1 = __ldg(wp + 1);
        #pragma unroll
        for (int r = 0; r < 8; r++) {
            u64 x2 = *reinterpret_cast<const u64*>(xb + r * DK + 2 * ip);
            acc2[r][0] = fma2(x2, wv0.x, acc2[r][0]);
            acc2[r][1] = fma2(x2, wv0.y, acc2[r][1]);
            acc2[r][2] = fma2(x2, wv1.x, acc2[r][2]);
            acc2[r][3] = fma2(x2, wv1.y, acc2[r][3]);
        }
    }

    float4 pw = __ldg(reinterpret_cast<const float4*>(p_W + j0));
    float pb  = __ldg(p_b);
    #pragma unroll
    for (int r = 0; r < 8; r++) {
        float l0, h0, l1, h1, l2, h2, l3, h3;
        unpack2(acc2[r][0], l0, h0);
        unpack2(acc2[r][1], l1, h1);
        unpack2(acc2[r][2], l2, h2);
        unpack2(acc2[r][3], l3, h3);
        float s = tanhf(l0 + h0) * pw.x + tanhf(l1 + h1) * pw.y
                + tanhf(l2 + h2) * pw.z + tanhf(l3 + h3) * pw.w;
        #pragma unroll
        for (int off = 16; off; off >>= 1)
            s += __shfl_xor_sync(0xffffffffu, s, off);
        if (jg == 0) {
            int gr = row0 + rg * 8 + r;
            out[gr] = 1.0f / (1.0f + expf(-s));
        }
    }

    if (tid < RT_ROWS) {
        int gr = row0 + tid;
        int bb = gr / TOUT;
        int tt = gr - bb * TOUT;
        out2[gr] = (float)__ldg(responses + bb * T + tt + 1);
    }
}

// ---------------- launch ----------------------------------------------------
extern "C" void kernel_launch(void* const* d_in, const int* in_sizes, int n_in,
                              void* d_out, int out_size) {
    const int*   skills    = (const int*)  d_in[0];
    const int*   responses = (const int*)  d_in[1];
    const float* k_emb     = (const float*)d_in[2];
    const float* v_emb     = (const float*)d_in[3];
    const float* Mk        = (const float*)d_in[4];
    const float* Mv0       = (const float*)d_in[5];
    const float* f_W       = (const float*)d_in[6];
    const float* f_b       = (const float*)d_in[7];
    const float* p_W       = (const float*)d_in[8];
    const float* p_b       = (const float*)d_in[9];
    const float* e_W       = (const float*)d_in[10];
    const float* e_b       = (const float*)d_in[11];
    const float* a_W       = (const float*)d_in[12];
    const float* a_b       = (const float*)d_in[13];

    float* pred_out = (float*)d_out;
    float* true_out = pred_out + (out_size / 2);

    pre_fused_kernel<<<PRE_BLOCKS, 256>>>(k_emb, v_emb, Mk,
                                          e_W, e_b, a_W, a_b);

    scan_kernel<<<SCAN_GRID, 128>>>(skills, responses, Mv0,
                                    k_emb, f_W, f_b);

    readout_kernel<<<NROWS / RT_ROWS, 256>>>(p_W, p_b, skills, responses,
                                             pred_out, true_out);
}

// round 11
// speedup vs baseline: 1.0321x; 1.0321x over previous
#include <cuda_runtime.h>
#include <cuda_bf16.h>
#include <cstdint>

// Problem constants
#define B    256
#define T    256
#define NQ   1000
#define DK   128
#define DV   128
#define CC   32
#define TOUT 255
#define NROWS (B * TOUT)         // 65280

typedef unsigned long long u64;

// ---------------- packed f32x2 helpers (sm_103a) --------------------------
__device__ __forceinline__ u64 pack2(float lo, float hi) {
    u64 r; asm("mov.b64 %0, {%1, %2};" : "=l"(r) : "f"(lo), "f"(hi)); return r;
}
__device__ __forceinline__ void unpack2(u64 v, float& lo, float& hi) {
    asm("mov.b64 {%0, %1}, %2;" : "=f"(lo), "=f"(hi) : "l"(v));
}
__device__ __forceinline__ u64 fma2(u64 a, u64 b, u64 c) {
    u64 d; asm("fma.rn.f32x2 %0, %1, %2, %3;" : "=l"(d) : "l"(a), "l"(b), "l"(c)); return d;
}

// ---------------- device scratch ------------------------------------------
__device__ __align__(16) float  g_wt[NQ * CC];        // softmax(k_emb @ Mk)
__device__ __align__(16) float  g_g [NQ * DK];        // k_emb @ f_W[128:] + f_b
__device__ __align__(16) float2 g_ea[2 * NQ * DV];    // (-sigmoid(vW_e), tanh(vW_a))
__device__ __align__(16) float  g_rt[NROWS * DV];     // rt scratch
__device__ __align__(16) u64    g_fw2[(DK / 2) * DK]; // f_W rows 0..127, i-pair packed

// ---------------- fused precompute (round-9 version, measured 20.4-20.8us) -
#define EA_BLOCKS 125
#define WT_BLOCKS 125
#define PG_BLOCKS 63
#define PK_BLOCKS 32
#define PRE_BLOCKS (EA_BLOCKS + WT_BLOCKS + PG_BLOCKS + PK_BLOCKS)

__global__ void __launch_bounds__(256)
pre_fused_kernel(const float* __restrict__ k_emb,
                 const float* __restrict__ v_emb,
                 const float* __restrict__ Mk,
                 const float* __restrict__ f_W,
                 const float* __restrict__ f_b,
                 const float* __restrict__ e_W,
                 const float* __restrict__ e_b,
                 const float* __restrict__ a_W,
                 const float* __restrict__ a_b) {
    __shared__ __align__(16) float sbuf[16 * DK];
    int bid = blockIdx.x;
    int tid = threadIdx.x;

    if (bid < EA_BLOCKS) {
        // ---- pre_ea: (-e, a) for 16 rows ----
        int row0 = bid * 16;
        int j  = tid & 127;
        int rh = tid >> 7;
        #pragma unroll
        for (int u = 0; u < 2; u++) {
            int idx = tid + u * 256;
            reinterpret_cast<float4*>(sbuf)[idx] =
                __ldg(reinterpret_cast<const float4*>(v_emb + row0 * DV) + idx);
        }
        __syncthreads();

        float acce[8], acca[8];
        float eb = __ldg(e_b + j), ab = __ldg(a_b + j);
        #pragma unroll
        for (int r = 0; r < 8; r++) { acce[r] = eb; acca[r] = ab; }

        const float* xb = sbuf + rh * 8 * DV;
        #pragma unroll 4
        for (int k = 0; k < DV; k += 4) {
            float we0 = __ldg(e_W + (k + 0) * DV + j);
            float we1 = __ldg(e_W + (k + 1) * DV + j);
            float we2 = __ldg(e_W + (k + 2) * DV + j);
            float we3 = __ldg(e_W + (k + 3) * DV + j);
            float wa0 = __ldg(a_W + (k + 0) * DV + j);
            float wa1 = __ldg(a_W + (k + 1) * DV + j);
            float wa2 = __ldg(a_W + (k + 2) * DV + j);
            float wa3 = __ldg(a_W + (k + 3) * DV + j);
            #pragma unroll
            for (int r = 0; r < 8; r++) {
                float4 xv = *reinterpret_cast<const float4*>(xb + r * DV + k);
                acce[r] = fmaf(xv.x, we0, acce[r]);
                acce[r] = fmaf(xv.y, we1, acce[r]);
                acce[r] = fmaf(xv.z, we2, acce[r]);
                acce[r] = fmaf(xv.w, we3, acce[r]);
                acca[r] = fmaf(xv.x, wa0, acca[r]);
                acca[r] = fmaf(xv.y, wa1, acca[r]);
                acca[r] = fmaf(xv.z, wa2, acca[r]);
                acca[r] = fmaf(xv.w, wa3, acca[r]);
            }
        }
        #pragma unroll
        for (int r = 0; r < 8; r++) {
            int gr = row0 + rh * 8 + r;
            g_ea[gr * DV + j] = make_float2(-1.0f / (1.0f + expf(-acce[r])),
                                            tanhf(acca[r]));
        }
    } else if (bid < EA_BLOCKS + WT_BLOCKS) {
        // ---- pre_wt: softmax(k_emb @ Mk), one q per warp ----
        int warp = tid >> 5;
        int lane = tid & 31;
        int q = (bid - EA_BLOCKS) * 8 + warp;
        const float* krow = k_emb + q * DK;
        float acc = 0.f;
        #pragma unroll 8
        for (int k = 0; k < DK; k++)
            acc = fmaf(__ldg(krow + k), __ldg(Mk + k * CC + lane), acc);
        float mx = acc;
        #pragma unroll
        for (int off = 16; off; off >>= 1)
            mx = fmaxf(mx, __shfl_xor_sync(0xffffffffu, mx, off));
        float e = expf(acc - mx);
        float s = e;
        #pragma unroll
        for (int off = 16; off; off >>= 1)
            s += __shfl_xor_sync(0xffffffffu, s, off);
        g_wt[q * CC + lane] = e / s;
    } else if (bid < EA_BLOCKS + WT_BLOCKS + PG_BLOCKS) {
        // ---- pre_g: g = k_emb @ f_W[128:] + f_b, 16 rows ----
        int row0 = (bid - EA_BLOCKS - WT_BLOCKS) * 16;
        int j  = tid & 127;
        int rh = tid >> 7;
        #pragma unroll
        for (int u = 0; u < 2; u++) {
            int idx = tid + u * 256;
            int r   = idx >> 5;
            int gr  = row0 + r; if (gr >= NQ) gr = NQ - 1;
            reinterpret_cast<float4*>(sbuf)[idx] =
                __ldg(reinterpret_cast<const float4*>(k_emb + gr * DK) + (idx & 31));
        }
        __syncthreads();

        float acc[8];
        float fb = __ldg(f_b + j);
        #pragma unroll
        for (int r = 0; r < 8; r++) acc[r] = fb;

        const float* xb = sbuf + rh * 8 * DK;
        #pragma unroll 4
        for (int k = 0; k < DK; k += 4) {
            float w0 = __ldg(f_W + (DK + k + 0) * DK + j);
            float w1 = __ldg(f_W + (DK + k + 1) * DK + j);
            float w2 = __ldg(f_W + (DK + k + 2) * DK + j);
            float w3 = __ldg(f_W + (DK + k + 3) * DK + j);
            #pragma unroll
            for (int r = 0; r < 8; r++) {
                float4 xv = *reinterpret_cast<const float4*>(xb + r * DK + k);
                acc[r] = fmaf(xv.x, w0, acc[r]);
                acc[r] = fmaf(xv.y, w1, acc[r]);
                acc[r] = fmaf(xv.z, w2, acc[r]);
                acc[r] = fmaf(xv.w, w3, acc[r]);
            }
        }
        #pragma unroll
        for (int r = 0; r < 8; r++) {
            int gr = row0 + rh * 8 + r;
            if (gr < NQ) g_g[gr * DK + j] = acc[r];
        }
    } else {
        // ---- pre_pack: f_W lower half -> u64 i-pairs ----
        int idx = (bid - EA_BLOCKS - WT_BLOCKS - PG_BLOCKS) * 256 + tid;
        int ip = idx >> 7;
        int j  = idx & 127;
        g_fw2[idx] = pack2(__ldg(f_W + (2 * ip) * DK + j),
                           __ldg(f_W + (2 * ip + 1) * DK + j));
    }
}

// ---------------- sequential scan: adjacent d-cols, unroll-8, 2 W bufs -----
// Thread td owns d0=2*td and d1=2*td+1 -> E refill is ONE LDG.128 (float4 =
// two adjacent float2) and the two rt outputs pack into ONE STG.64.

__device__ __forceinline__ void scan_loadW(int s, u64 W2[16]) {
    const ulonglong2* wp = reinterpret_cast<const ulonglong2*>(g_wt + s * CC);
    #pragma unroll
    for (int u = 0; u < 8; u++) {
        ulonglong2 v = __ldg(wp + u);
        W2[2 * u]     = v.x;
        W2[2 * u + 1] = v.y;
    }
}

__device__ __forceinline__ float scan_step(u64 m2[16], const u64 W2[16],
                                           float ne, float a) {
    u64 en2 = pack2(ne, ne);
    u64 a2  = pack2(a, a);
    u64 acc0 = 0ull, acc1 = 0ull;
    #pragma unroll
    for (int p = 0; p < 16; p++) {
        u64 mo = m2[p];
        if (p & 1) acc1 = fma2(W2[p], mo, acc1);
        else       acc0 = fma2(W2[p], mo, acc0);
        u64 tmp = fma2(mo, en2, a2);          // a - e*m
        m2[p] = fma2(W2[p], tmp, mo);         // m + w*(a - e*m)
    }
    float x0, x1, y0, y1;
    unpack2(acc0, x0, x1);
    unpack2(acc1, y0, y1);
    return (x0 + x1) + (y0 + y1);
}

__global__ void __launch_bounds__(128, 1)
scan_kernel(const int* __restrict__ skills,
            const int* __restrict__ responses,
            const float* __restrict__ Mv0) {
    int tid  = threadIdx.x;
    int half = tid >> 6;                 // 0/1 -> batch within block
    int td   = tid & 63;
    int b    = blockIdx.x * 2 + half;
    int d0   = 2 * td;
    int d1   = 2 * td + 1;

    u64 m0[16], m1[16];
    #pragma unroll
    for (int p = 0; p < 16; p++) {
        m0[p] = pack2(__ldg(Mv0 + (2 * p) * DV + d0),
                      __ldg(Mv0 + (2 * p + 1) * DV + d0));
        m1[p] = pack2(__ldg(Mv0 + (2 * p) * DV + d1),
                      __ldg(Mv0 + (2 * p + 1) * DV + d1));
    }

    const int* srow = skills + b * T;
    const int* rrow = responses + b * T;
    float* rtp = g_rt + (b * TOUT) * DV + d0;

    // E ring: slot k holds float4 (-e(d0), a(d0), -e(d1), a(d1)) for step t+k
    int    sE[8];
    float4 E[8];
    #pragma unroll
    for (int k = 0; k < 8; k++) {
        int s = __ldg(srow + k);
        int q = s + NQ * __ldg(rrow + k);
        sE[k] = s;
        E[k]  = __ldg(reinterpret_cast<const float4*>(g_ea + q * DV + d0));
    }
    int sCur = __ldg(srow + 8);
    int qCur = sCur + NQ * __ldg(rrow + 8);

    u64 WA[16], WB[16];
    scan_loadW(sE[0], WA);               // W for step 0

// consume slot k with Wc, preload Wn for step t+k+1, refill slot k for
// step t+8+k, advance index pair to step t+9+k.
#define SCAN_BODY_STEP(k, Wc, Wn)                                          \
    {                                                                      \
        scan_loadW(sE[((k) + 1) & 7], Wn);                                 \
        float s0 = scan_step(m0, Wc, E[k].x, E[k].y);                      \
        float s1 = scan_step(m1, Wc, E[k].z, E[k].w);                      \
        *reinterpret_cast<u64*>(rtp + (t + (k)) * DV) = pack2(s0, s1);     \
        E[k] = __ldg(reinterpret_cast<const float4*>(g_ea + qCur * DV + d0)); \
        sE[k] = sCur;                                                      \
        int ni = t + 9 + (k); if (ni > T - 1) ni = T - 1;                  \
        sCur = __ldg(srow + ni);                                           \
        qCur = sCur + NQ * __ldg(rrow + ni);                               \
    }

    // 31 bodies: steps 0..247
    for (int t = 0; t < 248; t += 8) {
        SCAN_BODY_STEP(0, WA, WB)
        SCAN_BODY_STEP(1, WB, WA)
        SCAN_BODY_STEP(2, WA, WB)
        SCAN_BODY_STEP(3, WB, WA)
        SCAN_BODY_STEP(4, WA, WB)
        SCAN_BODY_STEP(5, WB, WA)
        SCAN_BODY_STEP(6, WA, WB)
        SCAN_BODY_STEP(7, WB, WA)
    }
#undef SCAN_BODY_STEP

    // tail: steps 248..254 (slots 0..6; WA holds W(248) from last body)
    {
        const int t = 248;
#define SCAN_TAIL_STEP(k, Wc, Wn)                                          \
        {                                                                  \
            scan_loadW(sE[(k) + 1], Wn);                                   \
            float s0 = scan_step(m0, Wc, E[k].x, E[k].y);                  \
            float s1 = scan_step(m1, Wc, E[k].z, E[k].w);                  \
            *reinterpret_cast<u64*>(rtp + (t + (k)) * DV) = pack2(s0, s1); \
        }
        SCAN_TAIL_STEP(0, WA, WB)
        SCAN_TAIL_STEP(1, WB, WA)
        SCAN_TAIL_STEP(2, WA, WB)
        SCAN_TAIL_STEP(3, WB, WA)
        SCAN_TAIL_STEP(4, WA, WB)
        SCAN_TAIL_STEP(5, WB, WA)
        {
            float s0 = scan_step(m0, WA, E[6].x, E[6].y);
            float s1 = scan_step(m1, WA, E[6].z, E[6].w);
            *reinterpret_cast<u64*>(rtp + 254 * DV) = pack2(s0, s1);
        }
#undef SCAN_TAIL_STEP
    }
}

// ---------------- readout: GEMM + tanh + dot(p_W) + sigmoid ---------------
// ip-paired inner loop: one LDS.128 per row covers two ip (4 k values).
#define RT_ROWS 64
__global__ void __launch_bounds__(256)
readout_kernel(const float* __restrict__ p_W,
               const float* __restrict__ p_b,
               const int* __restrict__ skills,
               const int* __restrict__ responses,
               float* __restrict__ out,
               float* __restrict__ out2) {
    __shared__ __align__(16) float xs[RT_ROWS * DK];

    int tid  = threadIdx.x;
    int jg   = tid & 31;
    int rg   = tid >> 5;          // warp id 0..7
    int j0   = jg * 4;
    int row0 = blockIdx.x * RT_ROWS;

    {
        const float4* src = reinterpret_cast<const float4*>(g_rt + row0 * DK);
        float4* dst = reinterpret_cast<float4*>(xs);
        #pragma unroll
        for (int u = 0; u < (RT_ROWS * DK / 4) / 256; u++)
            dst[tid + u * 256] = src[tid + u * 256];
    }

    u64 acc2[8][4];
    #pragma unroll
    for (int r = 0; r < 8; r++) {
        int gr = row0 + rg * 8 + r;
        int bb = gr / TOUT;
        int tt = gr - bb * TOUT;
        int sk = __ldg(skills + bb * T + tt);
        float4 g = __ldg(reinterpret_cast<const float4*>(g_g + sk * DK + j0));
        acc2[r][0] = pack2(g.x, 0.f);
        acc2[r][1] = pack2(g.y, 0.f);
        acc2[r][2] = pack2(g.z, 0.f);
        acc2[r][3] = pack2(g.w, 0.f);
    }
    __syncthreads();

    const float* xb = xs + rg * 8 * DK;

    #pragma unroll 2
    for (int ip = 0; ip < DK / 2; ip += 2) {
        const ulonglong2* wpa =
            reinterpret_cast<const ulonglong2*>(g_fw2 + ip * DK + j0);
        const ulonglong2* wpb =
            reinterpret_cast<const ulonglong2*>(g_fw2 + (ip + 1) * DK + j0);
        ulonglong2 wa0 = __ldg(wpa);
        ulonglong2 wa1 = __ldg(wpa + 1);
        ulonglong2 wb0 = __ldg(wpb);
        ulonglong2 wb1 = __ldg(wpb + 1);
        #pragma unroll
        for (int r = 0; r < 8; r++) {
            ulonglong2 x2 =
                *reinterpret_cast<const ulonglong2*>(xb + r * DK + 2 * ip);
            acc2[r][0] = fma2(x2.x, wa0.x, acc2[r][0]);
            acc2[r][1] = fma2(x2.x, wa0.y, acc2[r][1]);
            acc2[r][2] = fma2(x2.x, wa1.x, acc2[r][2]);
            acc2[r][3] = fma2(x2.x, wa1.y, acc2[r][3]);
            acc2[r][0] = fma2(x2.y, wb0.x, acc2[r][0]);
            acc2[r][1] = fma2(x2.y, wb0.y, acc2[r][1]);
            acc2[r][2] = fma2(x2.y, wb1.x, acc2[r][2]);
            acc2[r][3] = fma2(x2.y, wb1.y, acc2[r][3]);
        }
    }

    float4 pw = __ldg(reinterpret_cast<const float4*>(p_W + j0));
    float pb  = __ldg(p_b);
    #pragma unroll
    for (int r = 0; r < 8; r++) {
        float l0, h0, l1, h1, l2, h2, l3, h3;
        unpack2(acc2[r][0], l0, h0);
        unpack2(acc2[r][1], l1, h1);
        unpack2(acc2[r][2], l2, h2);
        unpack2(acc2[r][3], l3, h3);
        float s = tanhf(l0 + h0) * pw.x + tanhf(l1 + h1) * pw.y
                + tanhf(l2 + h2) * pw.z + tanhf(l3 + h3) * pw.w;
        #pragma unroll
        for (int off = 16; off; off >>= 1)
            s += __shfl_xor_sync(0xffffffffu, s, off);
        if (jg == 0) {
            int gr = row0 + rg * 8 + r;
            out[gr] = 1.0f / (1.0f + expf(-s));
        }
    }

    if (tid < RT_ROWS) {
        int gr = row0 + tid;
        int bb = gr / TOUT;
        int tt = gr - bb * TOUT;
        out2[gr] = (float)__ldg(responses + bb * T + tt + 1);
    }
}

// ---------------- launch ----------------------------------------------------
extern "C" void kernel_launch(void* const* d_in, const int* in_sizes, int n_in,
                              void* d_out, int out_size) {
    const int*   skills    = (const int*)  d_in[0];
    const int*   responses = (const int*)  d_in[1];
    const float* k_emb     = (const float*)d_in[2];
    const float* v_emb     = (const float*)d_in[3];
    const float* Mk        = (const float*)d_in[4];
    const float* Mv0       = (const float*)d_in[5];
    const float* f_W       = (const float*)d_in[6];
    const float* f_b       = (const float*)d_in[7];
    const float* p_W       = (const float*)d_in[8];
    const float* p_b       = (const float*)d_in[9];
    const float* e_W       = (const float*)d_in[10];
    const float* e_b       = (const float*)d_in[11];
    const float* a_W       = (const float*)d_in[12];
    const float* a_b       = (const float*)d_in[13];

    float* pred_out = (float*)d_out;
    float* true_out = pred_out + (out_size / 2);

    pre_fused_kernel<<<PRE_BLOCKS, 256>>>(k_emb, v_emb, Mk, f_W, f_b,
                                          e_W, e_b, a_W, a_b);

    scan_kernel<<<B / 2, 128>>>(skills, responses, Mv0);

    readout_kernel<<<NROWS / RT_ROWS, 256>>>(p_W, p_b, skills, responses,
                                             pred_out, true_out);
}

// round 12
// speedup vs baseline: 1.0469x; 1.0143x over previous
#include <cuda_runtime.h>
#include <cuda_bf16.h>
#include <cstdint>

// Problem constants
#define B    256
#define T    256
#define NQ   1000
#define DK   128
#define DV   128
#define CC   32
#define TOUT 255
#define NROWS (B * TOUT)         // 65280

typedef unsigned long long u64;

// ---------------- packed f32x2 helpers (sm_103a) --------------------------
__device__ __forceinline__ u64 pack2(float lo, float hi) {
    u64 r; asm("mov.b64 %0, {%1, %2};" : "=l"(r) : "f"(lo), "f"(hi)); return r;
}
__device__ __forceinline__ void unpack2(u64 v, float& lo, float& hi) {
    asm("mov.b64 {%0, %1}, %2;" : "=f"(lo), "=f"(hi) : "l"(v));
}
__device__ __forceinline__ u64 fma2(u64 a, u64 b, u64 c) {
    u64 d; asm("fma.rn.f32x2 %0, %1, %2, %3;" : "=l"(d) : "l"(a), "l"(b), "l"(c)); return d;
}

// ---------------- device scratch ------------------------------------------
__device__ __align__(16) float  g_wt[NQ * CC];        // softmax(k_emb @ Mk)
__device__ __align__(16) float  g_g [NQ * DK];        // k_emb @ f_W[128:] + f_b
__device__ __align__(16) float2 g_ea[2 * NQ * DV];    // (-sigmoid(vW_e), tanh(vW_a))
__device__ __align__(16) float  g_rt[NROWS * DV];     // rt scratch
__device__ __align__(16) u64    g_fw2[(DK / 2) * DK]; // f_W rows 0..127, i-pair packed

// ---------------- fused precompute (round-9 version) -----------------------
#define EA_BLOCKS 125
#define WT_BLOCKS 125
#define PG_BLOCKS 63
#define PK_BLOCKS 32
#define PRE_BLOCKS (EA_BLOCKS + WT_BLOCKS + PG_BLOCKS + PK_BLOCKS)

__global__ void __launch_bounds__(256)
pre_fused_kernel(const float* __restrict__ k_emb,
                 const float* __restrict__ v_emb,
                 const float* __restrict__ Mk,
                 const float* __restrict__ f_W,
                 const float* __restrict__ f_b,
                 const float* __restrict__ e_W,
                 const float* __restrict__ e_b,
                 const float* __restrict__ a_W,
                 const float* __restrict__ a_b) {
    __shared__ __align__(16) float sbuf[16 * DK];
    int bid = blockIdx.x;
    int tid = threadIdx.x;

    if (bid < EA_BLOCKS) {
        // ---- pre_ea: (-e, a) for 16 rows ----
        int row0 = bid * 16;
        int j  = tid & 127;
        int rh = tid >> 7;
        #pragma unroll
        for (int u = 0; u < 2; u++) {
            int idx = tid + u * 256;
            reinterpret_cast<float4*>(sbuf)[idx] =
                __ldg(reinterpret_cast<const float4*>(v_emb + row0 * DV) + idx);
        }
        __syncthreads();

        float acce[8], acca[8];
        float eb = __ldg(e_b + j), ab = __ldg(a_b + j);
        #pragma unroll
        for (int r = 0; r < 8; r++) { acce[r] = eb; acca[r] = ab; }

        const float* xb = sbuf + rh * 8 * DV;
        #pragma unroll 4
        for (int k = 0; k < DV; k += 4) {
            float we0 = __ldg(e_W + (k + 0) * DV + j);
            float we1 = __ldg(e_W + (k + 1) * DV + j);
            float we2 = __ldg(e_W + (k + 2) * DV + j);
            float we3 = __ldg(e_W + (k + 3) * DV + j);
            float wa0 = __ldg(a_W + (k + 0) * DV + j);
            float wa1 = __ldg(a_W + (k + 1) * DV + j);
            float wa2 = __ldg(a_W + (k + 2) * DV + j);
            float wa3 = __ldg(a_W + (k + 3) * DV + j);
            #pragma unroll
            for (int r = 0; r < 8; r++) {
                float4 xv = *reinterpret_cast<const float4*>(xb + r * DV + k);
                acce[r] = fmaf(xv.x, we0, acce[r]);
                acce[r] = fmaf(xv.y, we1, acce[r]);
                acce[r] = fmaf(xv.z, we2, acce[r]);
                acce[r] = fmaf(xv.w, we3, acce[r]);
                acca[r] = fmaf(xv.x, wa0, acca[r]);
                acca[r] = fmaf(xv.y, wa1, acca[r]);
                acca[r] = fmaf(xv.z, wa2, acca[r]);
                acca[r] = fmaf(xv.w, wa3, acca[r]);
            }
        }
        #pragma unroll
        for (int r = 0; r < 8; r++) {
            int gr = row0 + rh * 8 + r;
            g_ea[gr * DV + j] = make_float2(-1.0f / (1.0f + expf(-acce[r])),
                                            tanhf(acca[r]));
        }
    } else if (bid < EA_BLOCKS + WT_BLOCKS) {
        // ---- pre_wt: softmax(k_emb @ Mk), one q per warp ----
        int warp = tid >> 5;
        int lane = tid & 31;
        int q = (bid - EA_BLOCKS) * 8 + warp;
        const float* krow = k_emb + q * DK;
        float acc = 0.f;
        #pragma unroll 8
        for (int k = 0; k < DK; k++)
            acc = fmaf(__ldg(krow + k), __ldg(Mk + k * CC + lane), acc);
        float mx = acc;
        #pragma unroll
        for (int off = 16; off; off >>= 1)
            mx = fmaxf(mx, __shfl_xor_sync(0xffffffffu, mx, off));
        float e = expf(acc - mx);
        float s = e;
        #pragma unroll
        for (int off = 16; off; off >>= 1)
            s += __shfl_xor_sync(0xffffffffu, s, off);
        g_wt[q * CC + lane] = e / s;
    } else if (bid < EA_BLOCKS + WT_BLOCKS + PG_BLOCKS) {
        // ---- pre_g: g = k_emb @ f_W[128:] + f_b, 16 rows ----
        int row0 = (bid - EA_BLOCKS - WT_BLOCKS) * 16;
        int j  = tid & 127;
        int rh = tid >> 7;
        #pragma unroll
        for (int u = 0; u < 2; u++) {
            int idx = tid + u * 256;
            int r   = idx >> 5;
            int gr  = row0 + r; if (gr >= NQ) gr = NQ - 1;
            reinterpret_cast<float4*>(sbuf)[idx] =
                __ldg(reinterpret_cast<const float4*>(k_emb + gr * DK) + (idx & 31));
        }
        __syncthreads();

        float acc[8];
        float fb = __ldg(f_b + j);
        #pragma unroll
        for (int r = 0; r < 8; r++) acc[r] = fb;

        const float* xb = sbuf + rh * 8 * DK;
        #pragma unroll 4
        for (int k = 0; k < DK; k += 4) {
            float w0 = __ldg(f_W + (DK + k + 0) * DK + j);
            float w1 = __ldg(f_W + (DK + k + 1) * DK + j);
            float w2 = __ldg(f_W + (DK + k + 2) * DK + j);
            float w3 = __ldg(f_W + (DK + k + 3) * DK + j);
            #pragma unroll
            for (int r = 0; r < 8; r++) {
                float4 xv = *reinterpret_cast<const float4*>(xb + r * DK + k);
                acc[r] = fmaf(xv.x, w0, acc[r]);
                acc[r] = fmaf(xv.y, w1, acc[r]);
                acc[r] = fmaf(xv.z, w2, acc[r]);
                acc[r] = fmaf(xv.w, w3, acc[r]);
            }
        }
        #pragma unroll
        for (int r = 0; r < 8; r++) {
            int gr = row0 + rh * 8 + r;
            if (gr < NQ) g_g[gr * DK + j] = acc[r];
        }
    } else {
        // ---- pre_pack: f_W lower half -> u64 i-pairs ----
        int idx = (bid - EA_BLOCKS - WT_BLOCKS - PG_BLOCKS) * 256 + tid;
        int ip = idx >> 7;
        int j  = idx & 127;
        g_fw2[idx] = pack2(__ldg(f_W + (2 * ip) * DK + j),
                           __ldg(f_W + (2 * ip + 1) * DK + j));
    }
}

// ---------------- sequential scan (round-9 version, byte-exact) ------------
__device__ __forceinline__ void scan_loadW(int s, u64 W2[16]) {
    const ulonglong2* wp = reinterpret_cast<const ulonglong2*>(g_wt + s * CC);
    #pragma unroll
    for (int u = 0; u < 8; u++) {
        ulonglong2 v = __ldg(wp + u);
        W2[2 * u]     = v.x;
        W2[2 * u + 1] = v.y;
    }
}

__device__ __forceinline__ float scan_step(u64 m2[16], const u64 W2[16],
                                           float ne, float a) {
    u64 en2 = pack2(ne, ne);
    u64 a2  = pack2(a, a);
    u64 acc0 = 0ull, acc1 = 0ull;
    #pragma unroll
    for (int p = 0; p < 16; p++) {
        u64 mo = m2[p];
        if (p & 1) acc1 = fma2(W2[p], mo, acc1);
        else       acc0 = fma2(W2[p], mo, acc0);
        u64 tmp = fma2(mo, en2, a2);          // a - e*m
        m2[p] = fma2(W2[p], tmp, mo);         // m + w*(a - e*m)
    }
    float x0, x1, y0, y1;
    unpack2(acc0, x0, x1);
    unpack2(acc1, y0, y1);
    return (x0 + x1) + (y0 + y1);
}

__global__ void __launch_bounds__(128, 1)
scan_kernel(const int* __restrict__ skills,
            const int* __restrict__ responses,
            const float* __restrict__ Mv0) {
    int tid  = threadIdx.x;
    int half = tid >> 6;                 // 0/1 -> batch within block
    int td   = tid & 63;
    int b    = blockIdx.x * 2 + half;
    int d0   = td;
    int d1   = td + 64;

    u64 m0[16], m1[16];
    #pragma unroll
    for (int p = 0; p < 16; p++) {
        m0[p] = pack2(__ldg(Mv0 + (2 * p) * DV + d0),
                      __ldg(Mv0 + (2 * p + 1) * DV + d0));
        m1[p] = pack2(__ldg(Mv0 + (2 * p) * DV + d1),
                      __ldg(Mv0 + (2 * p + 1) * DV + d1));
    }

    const int* srow = skills + b * T;
    const int* rrow = responses + b * T;
    float* rtp0 = g_rt + (b * TOUT) * DV + d0;
    float* rtp1 = g_rt + (b * TOUT) * DV + d1;

    int    sE[8];
    float2 E0[8], E1[8];
    #pragma unroll
    for (int k = 0; k < 8; k++) {
        int s = __ldg(srow + k);
        int q = s + NQ * __ldg(rrow + k);
        sE[k] = s;
        E0[k] = __ldg(g_ea + q * DV + d0);
        E1[k] = __ldg(g_ea + q * DV + d1);
    }
    int sCur = __ldg(srow + 8);
    int qCur = sCur + NQ * __ldg(rrow + 8);

    u64 WA[16], WB[16];
    scan_loadW(sE[0], WA);

#define SCAN_BODY_STEP(k, Wc, Wn)                                          \
    {                                                                      \
        scan_loadW(sE[((k) + 1) & 7], Wn);                                 \
        rtp0[(t + (k)) * DV] = scan_step(m0, Wc, E0[k].x, E0[k].y);        \
        rtp1[(t + (k)) * DV] = scan_step(m1, Wc, E1[k].x, E1[k].y);        \
        E0[k] = __ldg(g_ea + qCur * DV + d0);                              \
        E1[k] = __ldg(g_ea + qCur * DV + d1);                              \
        sE[k] = sCur;                                                      \
        int ni = t + 9 + (k); if (ni > T - 1) ni = T - 1;                  \
        sCur = __ldg(srow + ni);                                           \
        qCur = sCur + NQ * __ldg(rrow + ni);                               \
    }

    for (int t = 0; t < 248; t += 8) {
        SCAN_BODY_STEP(0, WA, WB)
        SCAN_BODY_STEP(1, WB, WA)
        SCAN_BODY_STEP(2, WA, WB)
        SCAN_BODY_STEP(3, WB, WA)
        SCAN_BODY_STEP(4, WA, WB)
        SCAN_BODY_STEP(5, WB, WA)
        SCAN_BODY_STEP(6, WA, WB)
        SCAN_BODY_STEP(7, WB, WA)
    }
#undef SCAN_BODY_STEP

    {
        const int t = 248;
#define SCAN_TAIL_STEP(k, Wc, Wn)                                          \
        {                                                                  \
            scan_loadW(sE[(k) + 1], Wn);                                   \
            rtp0[(t + (k)) * DV] = scan_step(m0, Wc, E0[k].x, E0[k].y);    \
            rtp1[(t + (k)) * DV] = scan_step(m1, Wc, E1[k].x, E1[k].y);    \
        }
        SCAN_TAIL_STEP(0, WA, WB)
        SCAN_TAIL_STEP(1, WB, WA)
        SCAN_TAIL_STEP(2, WA, WB)
        SCAN_TAIL_STEP(3, WB, WA)
        SCAN_TAIL_STEP(4, WA, WB)
        SCAN_TAIL_STEP(5, WB, WA)
        rtp0[254 * DV] = scan_step(m0, WA, E0[6].x, E0[6].y);
        rtp1[254 * DV] = scan_step(m1, WA, E1[6].x, E1[6].y);
#undef SCAN_TAIL_STEP
    }
}

// ---------------- readout: GEMM + tanh + dot(p_W) + sigmoid ---------------
// ONLY change vs round-9: ip-paired inner loop (one LDS.128 serves two ip).
#define RT_ROWS 64
__global__ void __launch_bounds__(256)
readout_kernel(const float* __restrict__ p_W,
               const float* __restrict__ p_b,
               const int* __restrict__ skills,
               const int* __restrict__ responses,
               float* __restrict__ out,
               float* __restrict__ out2) {
    __shared__ __align__(16) float xs[RT_ROWS * DK];

    int tid  = threadIdx.x;
    int jg   = tid & 31;
    int rg   = tid >> 5;          // warp id 0..7
    int j0   = jg * 4;
    int row0 = blockIdx.x * RT_ROWS;

    {
        const float4* src = reinterpret_cast<const float4*>(g_rt + row0 * DK);
        float4* dst = reinterpret_cast<float4*>(xs);
        #pragma unroll
        for (int u = 0; u < (RT_ROWS * DK / 4) / 256; u++)
            dst[tid + u * 256] = src[tid + u * 256];
    }

    u64 acc2[8][4];
    #pragma unroll
    for (int r = 0; r < 8; r++) {
        int gr = row0 + rg * 8 + r;
        int bb = gr / TOUT;
        int tt = gr - bb * TOUT;
        int sk = __ldg(skills + bb * T + tt);
        float4 g = __ldg(reinterpret_cast<const float4*>(g_g + sk * DK + j0));
        acc2[r][0] = pack2(g.x, 0.f);
        acc2[r][1] = pack2(g.y, 0.f);
        acc2[r][2] = pack2(g.z, 0.f);
        acc2[r][3] = pack2(g.w, 0.f);
    }
    __syncthreads();

    const float* xb = xs + rg * 8 * DK;

    #pragma unroll 2
    for (int ip = 0; ip < DK / 2; ip += 2) {
        const ulonglong2* wpa =
            reinterpret_cast<const ulonglong2*>(g_fw2 + ip * DK + j0);
        const ulonglong2* wpb =
            reinterpret_cast<const ulonglong2*>(g_fw2 + (ip + 1) * DK + j0);
        ulonglong2 wa0 = __ldg(wpa);
        ulonglong2 wa1 = __ldg(wpa + 1);
        ulonglong2 wb0 = __ldg(wpb);
        ulonglong2 wb1 = __ldg(wpb + 1);
        #pragma unroll
        for (int r = 0; r < 8; r++) {
            ulonglong2 x2 =
                *reinterpret_cast<const ulonglong2*>(xb + r * DK + 2 * ip);
            acc2[r][0] = fma2(x2.x, wa0.x, acc2[r][0]);
            acc2[r][1] = fma2(x2.x, wa0.y, acc2[r][1]);
            acc2[r][2] = fma2(x2.x, wa1.x, acc2[r][2]);
            acc2[r][3] = fma2(x2.x, wa1.y, acc2[r][3]);
            acc2[r][0] = fma2(x2.y, wb0.x, acc2[r][0]);
            acc2[r][1] = fma2(x2.y, wb0.y, acc2[r][1]);
            acc2[r][2] = fma2(x2.y, wb1.x, acc2[r][2]);
            acc2[r][3] = fma2(x2.y, wb1.y, acc2[r][3]);
        }
    }

    float4 pw = __ldg(reinterpret_cast<const float4*>(p_W + j0));
    float pb  = __ldg(p_b);
    #pragma unroll
    for (int r = 0; r < 8; r++) {
        float l0, h0, l1, h1, l2, h2, l3, h3;
        unpack2(acc2[r][0], l0, h0);
        unpack2(acc2[r][1], l1, h1);
        unpack2(acc2[r][2], l2, h2);
        unpack2(acc2[r][3], l3, h3);
        float s = tanhf(l0 + h0) * pw.x + tanhf(l1 + h1) * pw.y
                + tanhf(l2 + h2) * pw.z + tanhf(l3 + h3) * pw.w;
        #pragma unroll
        for (int off = 16; off; off >>= 1)
            s += __shfl_xor_sync(0xffffffffu, s, off);
        if (jg == 0) {
            int gr = row0 + rg * 8 + r;
            out[gr] = 1.0f / (1.0f + expf(-s));
        }
    }

    if (tid < RT_ROWS) {
        int gr = row0 + tid;
        int bb = gr / TOUT;
        int tt = gr - bb * TOUT;
        out2[gr] = (float)__ldg(responses + bb * T + tt + 1);
    }
}

// ---------------- launch ----------------------------------------------------
extern "C" void kernel_launch(void* const* d_in, const int* in_sizes, int n_in,
                              void* d_out, int out_size) {
    const int*   skills    = (const int*)  d_in[0];
    const int*   responses = (const int*)  d_in[1];
    const float* k_emb     = (const float*)d_in[2];
    const float* v_emb     = (const float*)d_in[3];
    const float* Mk        = (const float*)d_in[4];
    const float* Mv0       = (const float*)d_in[5];
    const float* f_W       = (const float*)d_in[6];
    const float* f_b       = (const float*)d_in[7];
    const float* p_W       = (const float*)d_in[8];
    const float* p_b       = (const float*)d_in[9];
    const float* e_W       = (const float*)d_in[10];
    const float* e_b       = (const float*)d_in[11];
    const float* a_W       = (const float*)d_in[12];
    const float* a_b       = (const float*)d_in[13];

    float* pred_out = (float*)d_out;
    float* true_out = pred_out + (out_size / 2);

    pre_fused_kernel<<<PRE_BLOCKS, 256>>>(k_emb, v_emb, Mk, f_W, f_b,
                                          e_W, e_b, a_W, a_b);

    scan_kernel<<<B / 2, 128>>>(skills, responses, Mv0);

    readout_kernel<<<NROWS / RT_ROWS, 256>>>(p_W, p_b, skills, responses,
                                             pred_out, true_out);
}

// round 13
// speedup vs baseline: 1.0487x; 1.0018x over previous
#include <cuda_runtime.h>
#include <cuda_bf16.h>
#include <cstdint>

// Problem constants
#define B    256
#define T    256
#define NQ   1000
#define DK   128
#define DV   128
#define CC   32
#define TOUT 255
#define NROWS (B * TOUT)         // 65280

typedef unsigned long long u64;

// ---------------- packed f32x2 helpers (sm_103a) --------------------------
__device__ __forceinline__ u64 pack2(float lo, float hi) {
    u64 r; asm("mov.b64 %0, {%1, %2};" : "=l"(r) : "f"(lo), "f"(hi)); return r;
}
__device__ __forceinline__ void unpack2(u64 v, float& lo, float& hi) {
    asm("mov.b64 {%0, %1}, %2;" : "=f"(lo), "=f"(hi) : "l"(v));
}
__device__ __forceinline__ u64 fma2(u64 a, u64 b, u64 c) {
    u64 d; asm("fma.rn.f32x2 %0, %1, %2, %3;" : "=l"(d) : "l"(a), "l"(b), "l"(c)); return d;
}

// ---------------- device scratch ------------------------------------------
__device__ __align__(16) float  g_wt[NQ * CC];        // softmax(k_emb @ Mk)
__device__ __align__(16) float  g_g [NQ * DK];        // k_emb @ f_W[128:] + f_b
__device__ __align__(16) float2 g_ea[2 * NQ * DV];    // (-sigmoid(vW_e), tanh(vW_a))
__device__ __align__(16) float  g_rt[NROWS * DV];     // rt scratch
__device__ __align__(16) u64    g_fw2[(DK / 2) * DK]; // f_W rows 0..127, i-pair packed

// ---------------- fused precompute: j-split EA/PG for latency hiding -------
// Roles (256 threads each):
//   [0,250)    : pre_ea  (16 rows x 64 j-cols each; 2 blocks per row-tile)
//   [250,375)  : pre_wt  (8 question rows each, one per warp)
//   [375,501)  : pre_g   (16 rows x 64 j-cols each, row clamp at 1000)
//   [501,533)  : pre_pack (256 entries of g_fw2 each)
#define EA_BLOCKS 250
#define WT_BLOCKS 125
#define PG_BLOCKS 126
#define PK_BLOCKS 32
#define PRE_BLOCKS (EA_BLOCKS + WT_BLOCKS + PG_BLOCKS + PK_BLOCKS)

__global__ void __launch_bounds__(256)
pre_fused_kernel(const float* __restrict__ k_emb,
                 const float* __restrict__ v_emb,
                 const float* __restrict__ Mk,
                 const float* __restrict__ f_W,
                 const float* __restrict__ f_b,
                 const float* __restrict__ e_W,
                 const float* __restrict__ e_b,
                 const float* __restrict__ a_W,
                 const float* __restrict__ a_b) {
    __shared__ __align__(16) float sbuf[16 * DK];
    int bid = blockIdx.x;
    int tid = threadIdx.x;

    if (bid < EA_BLOCKS) {
        // ---- pre_ea: (-e, a) for 16 rows, 64 j-columns per block ----
        int row0 = (bid >> 1) * 16;
        int j    = (bid & 1) * 64 + (tid & 63);
        int rg   = tid >> 6;                       // 4 groups x 4 rows
        // stage 16x128 floats = 512 float4
        #pragma unroll
        for (int u = 0; u < 2; u++) {
            int idx = tid + u * 256;
            reinterpret_cast<float4*>(sbuf)[idx] =
                __ldg(reinterpret_cast<const float4*>(v_emb + row0 * DV) + idx);
        }
        __syncthreads();

        float acce[4], acca[4];
        float eb = __ldg(e_b + j), ab = __ldg(a_b + j);
        #pragma unroll
        for (int r = 0; r < 4; r++) { acce[r] = eb; acca[r] = ab; }

        const float* xb = sbuf + rg * 4 * DV;
        #pragma unroll 4
        for (int k = 0; k < DV; k += 4) {
            float we0 = __ldg(e_W + (k + 0) * DV + j);
            float we1 = __ldg(e_W + (k + 1) * DV + j);
            float we2 = __ldg(e_W + (k + 2) * DV + j);
            float we3 = __ldg(e_W + (k + 3) * DV + j);
            float wa0 = __ldg(a_W + (k + 0) * DV + j);
            float wa1 = __ldg(a_W + (k + 1) * DV + j);
            float wa2 = __ldg(a_W + (k + 2) * DV + j);
            float wa3 = __ldg(a_W + (k + 3) * DV + j);
            #pragma unroll
            for (int r = 0; r < 4; r++) {
                float4 xv = *reinterpret_cast<const float4*>(xb + r * DV + k);
                acce[r] = fmaf(xv.x, we0, acce[r]);
                acce[r] = fmaf(xv.y, we1, acce[r]);
                acce[r] = fmaf(xv.z, we2, acce[r]);
                acce[r] = fmaf(xv.w, we3, acce[r]);
                acca[r] = fmaf(xv.x, wa0, acca[r]);
                acca[r] = fmaf(xv.y, wa1, acca[r]);
                acca[r] = fmaf(xv.z, wa2, acca[r]);
                acca[r] = fmaf(xv.w, wa3, acca[r]);
            }
        }
        #pragma unroll
        for (int r = 0; r < 4; r++) {
            int gr = row0 + rg * 4 + r;
            g_ea[gr * DV + j] = make_float2(-1.0f / (1.0f + expf(-acce[r])),
                                            tanhf(acca[r]));
        }
    } else if (bid < EA_BLOCKS + WT_BLOCKS) {
        // ---- pre_wt: softmax(k_emb @ Mk), one q per warp ----
        int warp = tid >> 5;
        int lane = tid & 31;
        int q = (bid - EA_BLOCKS) * 8 + warp;
        const float* krow = k_emb + q * DK;
        float acc = 0.f;
        #pragma unroll 8
        for (int k = 0; k < DK; k++)
            acc = fmaf(__ldg(krow + k), __ldg(Mk + k * CC + lane), acc);
        float mx = acc;
        #pragma unroll
        for (int off = 16; off; off >>= 1)
            mx = fmaxf(mx, __shfl_xor_sync(0xffffffffu, mx, off));
        float e = expf(acc - mx);
        float s = e;
        #pragma unroll
        for (int off = 16; off; off >>= 1)
            s += __shfl_xor_sync(0xffffffffu, s, off);
        g_wt[q * CC + lane] = e / s;
    } else if (bid < EA_BLOCKS + WT_BLOCKS + PG_BLOCKS) {
        // ---- pre_g: g = k_emb @ f_W[128:] + f_b, 16 rows x 64 j-cols ----
        int role = bid - EA_BLOCKS - WT_BLOCKS;
        int row0 = (role >> 1) * 16;
        int j    = (role & 1) * 64 + (tid & 63);
        int rg   = tid >> 6;
        #pragma unroll
        for (int u = 0; u < 2; u++) {
            int idx = tid + u * 256;
            int r   = idx >> 5;
            int gr  = row0 + r; if (gr >= NQ) gr = NQ - 1;
            reinterpret_cast<float4*>(sbuf)[idx] =
                __ldg(reinterpret_cast<const float4*>(k_emb + gr * DK) + (idx & 31));
        }
        __syncthreads();

        float acc[4];
        float fb = __ldg(f_b + j);
        #pragma unroll
        for (int r = 0; r < 4; r++) acc[r] = fb;

        const float* xb = sbuf + rg * 4 * DK;
        #pragma unroll 4
        for (int k = 0; k < DK; k += 4) {
            float w0 = __ldg(f_W + (DK + k + 0) * DK + j);
            float w1 = __ldg(f_W + (DK + k + 1) * DK + j);
            float w2 = __ldg(f_W + (DK + k + 2) * DK + j);
            float w3 = __ldg(f_W + (DK + k + 3) * DK + j);
            #pragma unroll
            for (int r = 0; r < 4; r++) {
                float4 xv = *reinterpret_cast<const float4*>(xb + r * DK + k);
                acc[r] = fmaf(xv.x, w0, acc[r]);
                acc[r] = fmaf(xv.y, w1, acc[r]);
                acc[r] = fmaf(xv.z, w2, acc[r]);
                acc[r] = fmaf(xv.w, w3, acc[r]);
            }
        }
        #pragma unroll
        for (int r = 0; r < 4; r++) {
            int gr = row0 + rg * 4 + r;
            if (gr < NQ) g_g[gr * DK + j] = acc[r];
        }
    } else {
        // ---- pre_pack: f_W lower half -> u64 i-pairs ----
        int idx = (bid - EA_BLOCKS - WT_BLOCKS - PG_BLOCKS) * 256 + tid;
        int ip = idx >> 7;
        int j  = idx & 127;
        g_fw2[idx] = pack2(__ldg(f_W + (2 * ip) * DK + j),
                           __ldg(f_W + (2 * ip + 1) * DK + j));
    }
}

// ---------------- sequential scan (round-9/12 version, byte-exact) ---------
__device__ __forceinline__ void scan_loadW(int s, u64 W2[16]) {
    const ulonglong2* wp = reinterpret_cast<const ulonglong2*>(g_wt + s * CC);
    #pragma unroll
    for (int u = 0; u < 8; u++) {
        ulonglong2 v = __ldg(wp + u);
        W2[2 * u]     = v.x;
        W2[2 * u + 1] = v.y;
    }
}

__device__ __forceinline__ float scan_step(u64 m2[16], const u64 W2[16],
                                           float ne, float a) {
    u64 en2 = pack2(ne, ne);
    u64 a2  = pack2(a, a);
    u64 acc0 = 0ull, acc1 = 0ull;
    #pragma unroll
    for (int p = 0; p < 16; p++) {
        u64 mo = m2[p];
        if (p & 1) acc1 = fma2(W2[p], mo, acc1);
        else       acc0 = fma2(W2[p], mo, acc0);
        u64 tmp = fma2(mo, en2, a2);          // a - e*m
        m2[p] = fma2(W2[p], tmp, mo);         // m + w*(a - e*m)
    }
    float x0, x1, y0, y1;
    unpack2(acc0, x0, x1);
    unpack2(acc1, y0, y1);
    return (x0 + x1) + (y0 + y1);
}

__global__ void __launch_bounds__(128, 1)
scan_kernel(const int* __restrict__ skills,
            const int* __restrict__ responses,
            const float* __restrict__ Mv0) {
    int tid  = threadIdx.x;
    int half = tid >> 6;                 // 0/1 -> batch within block
    int td   = tid & 63;
    int b    = blockIdx.x * 2 + half;
    int d0   = td;
    int d1   = td + 64;

    u64 m0[16], m1[16];
    #pragma unroll
    for (int p = 0; p < 16; p++) {
        m0[p] = pack2(__ldg(Mv0 + (2 * p) * DV + d0),
                      __ldg(Mv0 + (2 * p + 1) * DV + d0));
        m1[p] = pack2(__ldg(Mv0 + (2 * p) * DV + d1),
                      __ldg(Mv0 + (2 * p + 1) * DV + d1));
    }

    const int* srow = skills + b * T;
    const int* rrow = responses + b * T;
    float* rtp0 = g_rt + (b * TOUT) * DV + d0;
    float* rtp1 = g_rt + (b * TOUT) * DV + d1;

    int    sE[8];
    float2 E0[8], E1[8];
    #pragma unroll
    for (int k = 0; k < 8; k++) {
        int s = __ldg(srow + k);
        int q = s + NQ * __ldg(rrow + k);
        sE[k] = s;
        E0[k] = __ldg(g_ea + q * DV + d0);
        E1[k] = __ldg(g_ea + q * DV + d1);
    }
    int sCur = __ldg(srow + 8);
    int qCur = sCur + NQ * __ldg(rrow + 8);

    u64 WA[16], WB[16];
    scan_loadW(sE[0], WA);

#define SCAN_BODY_STEP(k, Wc, Wn)                                          \
    {                                                                      \
        scan_loadW(sE[((k) + 1) & 7], Wn);                                 \
        rtp0[(t + (k)) * DV] = scan_step(m0, Wc, E0[k].x, E0[k].y);        \
        rtp1[(t + (k)) * DV] = scan_step(m1, Wc, E1[k].x, E1[k].y);        \
        E0[k] = __ldg(g_ea + qCur * DV + d0);                              \
        E1[k] = __ldg(g_ea + qCur * DV + d1);                              \
        sE[k] = sCur;                                                      \
        int ni = t + 9 + (k); if (ni > T - 1) ni = T - 1;                  \
        sCur = __ldg(srow + ni);                                           \
        qCur = sCur + NQ * __ldg(rrow + ni);                               \
    }

    for (int t = 0; t < 248; t += 8) {
        SCAN_BODY_STEP(0, WA, WB)
        SCAN_BODY_STEP(1, WB, WA)
        SCAN_BODY_STEP(2, WA, WB)
        SCAN_BODY_STEP(3, WB, WA)
        SCAN_BODY_STEP(4, WA, WB)
        SCAN_BODY_STEP(5, WB, WA)
        SCAN_BODY_STEP(6, WA, WB)
        SCAN_BODY_STEP(7, WB, WA)
    }
#undef SCAN_BODY_STEP

    {
        const int t = 248;
#define SCAN_TAIL_STEP(k, Wc, Wn)                                          \
        {                                                                  \
            scan_loadW(sE[(k) + 1], Wn);                                   \
            rtp0[(t + (k)) * DV] = scan_step(m0, Wc, E0[k].x, E0[k].y);    \
            rtp1[(t + (k)) * DV] = scan_step(m1, Wc, E1[k].x, E1[k].y);    \
        }
        SCAN_TAIL_STEP(0, WA, WB)
        SCAN_TAIL_STEP(1, WB, WA)
        SCAN_TAIL_STEP(2, WA, WB)
        SCAN_TAIL_STEP(3, WB, WA)
        SCAN_TAIL_STEP(4, WA, WB)
        SCAN_TAIL_STEP(5, WB, WA)
        rtp0[254 * DV] = scan_step(m0, WA, E0[6].x, E0[6].y);
        rtp1[254 * DV] = scan_step(m1, WA, E1[6].x, E1[6].y);
#undef SCAN_TAIL_STEP
    }
}

// ---------------- readout (round-12 version, byte-exact) -------------------
#define RT_ROWS 64
__global__ void __launch_bounds__(256)
readout_kernel(const float* __restrict__ p_W,
               const float* __restrict__ p_b,
               const int* __restrict__ skills,
               const int* __restrict__ responses,
               float* __restrict__ out,
               float* __restrict__ out2) {
    __shared__ __align__(16) float xs[RT_ROWS * DK];

    int tid  = threadIdx.x;
    int jg   = tid & 31;
    int rg   = tid >> 5;          // warp id 0..7
    int j0   = jg * 4;
    int row0 = blockIdx.x * RT_ROWS;

    {
        const float4* src = reinterpret_cast<const float4*>(g_rt + row0 * DK);
        float4* dst = reinterpret_cast<float4*>(xs);
        #pragma unroll
        for (int u = 0; u < (RT_ROWS * DK / 4) / 256; u++)
            dst[tid + u * 256] = src[tid + u * 256];
    }

    u64 acc2[8][4];
    #pragma unroll
    for (int r = 0; r < 8; r++) {
        int gr = row0 + rg * 8 + r;
        int bb = gr / TOUT;
        int tt = gr - bb * TOUT;
        int sk = __ldg(skills + bb * T + tt);
        float4 g = __ldg(reinterpret_cast<const float4*>(g_g + sk * DK + j0));
        acc2[r][0] = pack2(g.x, 0.f);
        acc2[r][1] = pack2(g.y, 0.f);
        acc2[r][2] = pack2(g.z, 0.f);
        acc2[r][3] = pack2(g.w, 0.f);
    }
    __syncthreads();

    const float* xb = xs + rg * 8 * DK;

    #pragma unroll 2
    for (int ip = 0; ip < DK / 2; ip += 2) {
        const ulonglong2* wpa =
            reinterpret_cast<const ulonglong2*>(g_fw2 + ip * DK + j0);
        const ulonglong2* wpb =
            reinterpret_cast<const ulonglong2*>(g_fw2 + (ip + 1) * DK + j0);
        ulonglong2 wa0 = __ldg(wpa);
        ulonglong2 wa1 = __ldg(wpa + 1);
        ulonglong2 wb0 = __ldg(wpb);
        ulonglong2 wb1 = __ldg(wpb + 1);
        #pragma unroll
        for (int r = 0; r < 8; r++) {
            ulonglong2 x2 =
                *reinterpret_cast<const ulonglong2*>(xb + r * DK + 2 * ip);
            acc2[r][0] = fma2(x2.x, wa0.x, acc2[r][0]);
            acc2[r][1] = fma2(x2.x, wa0.y, acc2[r][1]);
            acc2[r][2] = fma2(x2.x, wa1.x, acc2[r][2]);
            acc2[r][3] = fma2(x2.x, wa1.y, acc2[r][3]);
            acc2[r][0] = fma2(x2.y, wb0.x, acc2[r][0]);
            acc2[r][1] = fma2(x2.y, wb0.y, acc2[r][1]);
            acc2[r][2] = fma2(x2.y, wb1.x, acc2[r][2]);
            acc2[r][3] = fma2(x2.y, wb1.y, acc2[r][3]);
        }
    }

    float4 pw = __ldg(reinterpret_cast<const float4*>(p_W + j0));
    float pb  = __ldg(p_b);
    #pragma unroll
    for (int r = 0; r < 8; r++) {
        float l0, h0, l1, h1, l2, h2, l3, h3;
        unpack2(acc2[r][0], l0, h0);
        unpack2(acc2[r][1], l1, h1);
        unpack2(acc2[r][2], l2, h2);
        unpack2(acc2[r][3], l3, h3);
        float s = tanhf(l0 + h0) * pw.x + tanhf(l1 + h1) * pw.y
                + tanhf(l2 + h2) * pw.z + tanhf(l3 + h3) * pw.w;
        #pragma unroll
        for (int off = 16; off; off >>= 1)
            s += __shfl_xor_sync(0xffffffffu, s, off);
        if (jg == 0) {
            int gr = row0 + rg * 8 + r;
            out[gr] = 1.0f / (1.0f + expf(-s));
        }
    }

    if (tid < RT_ROWS) {
        int gr = row0 + tid;
        int bb = gr / TOUT;
        int tt = gr - bb * TOUT;
        out2[gr] = (float)__ldg(responses + bb * T + tt + 1);
    }
}

// ---------------- launch ----------------------------------------------------
extern "C" void kernel_launch(void* const* d_in, const int* in_sizes, int n_in,
                              void* d_out, int out_size) {
    const int*   skills    = (const int*)  d_in[0];
    const int*   responses = (const int*)  d_in[1];
    const float* k_emb     = (const float*)d_in[2];
    const float* v_emb     = (const float*)d_in[3];
    const float* Mk        = (const float*)d_in[4];
    const float* Mv0       = (const float*)d_in[5];
    const float* f_W       = (const float*)d_in[6];
    const float* f_b       = (const float*)d_in[7];
    const float* p_W       = (const float*)d_in[8];
    const float* p_b       = (const float*)d_in[9];
    const float* e_W       = (const float*)d_in[10];
    const float* e_b       = (const float*)d_in[11];
    const float* a_W       = (const float*)d_in[12];
    const float* a_b       = (const float*)d_in[13];

    float* pred_out = (float*)d_out;
    float* true_out = pred_out + (out_size / 2);

    pre_fused_kernel<<<PRE_BLOCKS, 256>>>(k_emb, v_emb, Mk, f_W, f_b,
                                          e_W, e_b, a_W, a_b);

    scan_kernel<<<B / 2, 128>>>(skills, responses, Mv0);

    readout_kernel<<<NROWS / RT_ROWS, 256>>>(p_W, p_b, skills, responses,
                                             pred_out, true_out);
}

// round 14
// speedup vs baseline: 1.3608x; 1.2976x over previous
#include <cuda_runtime.h>
#include <cuda_bf16.h>
#include <cstdint>

// Problem constants
#define B    256
#define T    256
#define NQ   1000
#define DK   128
#define DV   128
#define CC   32
#define TOUT 255
#define NROWS (B * TOUT)         // 65280

typedef unsigned long long u64;
typedef unsigned int u32;

// ---------------- packed f32x2 helpers (sm_103a) --------------------------
__device__ __forceinline__ u64 pack2(float lo, float hi) {
    u64 r; asm("mov.b64 %0, {%1, %2};" : "=l"(r) : "f"(lo), "f"(hi)); return r;
}
__device__ __forceinline__ void unpack2(u64 v, float& lo, float& hi) {
    asm("mov.b64 {%0, %1}, %2;" : "=f"(lo), "=f"(hi) : "l"(v));
}
__device__ __forceinline__ u64 fma2(u64 a, u64 b, u64 c) {
    u64 d; asm("fma.rn.f32x2 %0, %1, %2, %3;" : "=l"(d) : "l"(a), "l"(b), "l"(c)); return d;
}
// pack two fp32 -> bf16x2 register: first arg -> LOWER half (k even), second -> upper.
__device__ __forceinline__ u32 bfpack(float lo, float hi) {
    u32 r; asm("cvt.rn.bf16x2.f32 %0, %1, %2;" : "=r"(r) : "f"(hi), "f"(lo)); return r;
}

// ---------------- device scratch ------------------------------------------
__device__ __align__(16) float  g_wt[NQ * CC];        // softmax(k_emb @ Mk)
__device__ __align__(16) float  g_g [NQ * DK];        // k_emb @ f_W[128:] + f_b
__device__ __align__(16) float2 g_ea[2 * NQ * DV];    // (-sigmoid(vW_e), tanh(vW_a))
__device__ __align__(16) float  g_rt[NROWS * DV];     // rt scratch
__device__ __align__(16) u64    g_bf[16 * 16 * 32];   // f_W bf16 hi/lo mma B-fragments

// ---------------- fused precompute (round-9 EA/WT/PG + BF role) ------------
#define EA_BLOCKS 125
#define WT_BLOCKS 125
#define PG_BLOCKS 63
#define BF_BLOCKS 32
#define PRE_BLOCKS (EA_BLOCKS + WT_BLOCKS + PG_BLOCKS + BF_BLOCKS)

__global__ void __launch_bounds__(256)
pre_fused_kernel(const float* __restrict__ k_emb,
                 const float* __restrict__ v_emb,
                 const float* __restrict__ Mk,
                 const float* __restrict__ f_W,
                 const float* __restrict__ f_b,
                 const float* __restrict__ e_W,
                 const float* __restrict__ e_b,
                 const float* __restrict__ a_W,
                 const float* __restrict__ a_b) {
    __shared__ __align__(16) float sbuf[16 * DK];
    int bid = blockIdx.x;
    int tid = threadIdx.x;

    if (bid < EA_BLOCKS) {
        // ---- pre_ea: (-e, a) for 16 rows ----
        int row0 = bid * 16;
        int j  = tid & 127;
        int rh = tid >> 7;
        #pragma unroll
        for (int u = 0; u < 2; u++) {
            int idx = tid + u * 256;
            reinterpret_cast<float4*>(sbuf)[idx] =
                __ldg(reinterpret_cast<const float4*>(v_emb + row0 * DV) + idx);
        }
        __syncthreads();

        float acce[8], acca[8];
        float eb = __ldg(e_b + j), ab = __ldg(a_b + j);
        #pragma unroll
        for (int r = 0; r < 8; r++) { acce[r] = eb; acca[r] = ab; }

        const float* xb = sbuf + rh * 8 * DV;
        #pragma unroll 4
        for (int k = 0; k < DV; k += 4) {
            float we0 = __ldg(e_W + (k + 0) * DV + j);
            float we1 = __ldg(e_W + (k + 1) * DV + j);
            float we2 = __ldg(e_W + (k + 2) * DV + j);
            float we3 = __ldg(e_W + (k + 3) * DV + j);
            float wa0 = __ldg(a_W + (k + 0) * DV + j);
            float wa1 = __ldg(a_W + (k + 1) * DV + j);
            float wa2 = __ldg(a_W + (k + 2) * DV + j);
            float wa3 = __ldg(a_W + (k + 3) * DV + j);
            #pragma unroll
            for (int r = 0; r < 8; r++) {
                float4 xv = *reinterpret_cast<const float4*>(xb + r * DV + k);
                acce[r] = fmaf(xv.x, we0, acce[r]);
                acce[r] = fmaf(xv.y, we1, acce[r]);
                acce[r] = fmaf(xv.z, we2, acce[r]);
                acce[r] = fmaf(xv.w, we3, acce[r]);
                acca[r] = fmaf(xv.x, wa0, acca[r]);
                acca[r] = fmaf(xv.y, wa1, acca[r]);
                acca[r] = fmaf(xv.z, wa2, acca[r]);
                acca[r] = fmaf(xv.w, wa3, acca[r]);
            }
        }
        #pragma unroll
        for (int r = 0; r < 8; r++) {
            int gr = row0 + rh * 8 + r;
            g_ea[gr * DV + j] = make_float2(-1.0f / (1.0f + expf(-acce[r])),
                                            tanhf(acca[r]));
        }
    } else if (bid < EA_BLOCKS + WT_BLOCKS) {
        // ---- pre_wt: softmax(k_emb @ Mk), one q per warp ----
        int warp = tid >> 5;
        int lane = tid & 31;
        int q = (bid - EA_BLOCKS) * 8 + warp;
        const float* krow = k_emb + q * DK;
        float acc = 0.f;
        #pragma unroll 8
        for (int k = 0; k < DK; k++)
            acc = fmaf(__ldg(krow + k), __ldg(Mk + k * CC + lane), acc);
        float mx = acc;
        #pragma unroll
        for (int off = 16; off; off >>= 1)
            mx = fmaxf(mx, __shfl_xor_sync(0xffffffffu, mx, off));
        float e = expf(acc - mx);
        float s = e;
        #pragma unroll
        for (int off = 16; off; off >>= 1)
            s += __shfl_xor_sync(0xffffffffu, s, off);
        g_wt[q * CC + lane] = e / s;
    } else if (bid < EA_BLOCKS + WT_BLOCKS + PG_BLOCKS) {
        // ---- pre_g: g = k_emb @ f_W[128:] + f_b, 16 rows ----
        int row0 = (bid - EA_BLOCKS - WT_BLOCKS) * 16;
        int j  = tid & 127;
        int rh = tid >> 7;
        #pragma unroll
        for (int u = 0; u < 2; u++) {
            int idx = tid + u * 256;
            int r   = idx >> 5;
            int gr  = row0 + r; if (gr >= NQ) gr = NQ - 1;
            reinterpret_cast<float4*>(sbuf)[idx] =
                __ldg(reinterpret_cast<const float4*>(k_emb + gr * DK) + (idx & 31));
        }
        __syncthreads();

        float acc[8];
        float fb = __ldg(f_b + j);
        #pragma unroll
        for (int r = 0; r < 8; r++) acc[r] = fb;

        const float* xb = sbuf + rh * 8 * DK;
        #pragma unroll 4
        for (int k = 0; k < DK; k += 4) {
            float w0 = __ldg(f_W + (DK + k + 0) * DK + j);
            float w1 = __ldg(f_W + (DK + k + 1) * DK + j);
            float w2 = __ldg(f_W + (DK + k + 2) * DK + j);
            float w3 = __ldg(f_W + (DK + k + 3) * DK + j);
            #pragma unroll
            for (int r = 0; r < 8; r++) {
                float4 xv = *reinterpret_cast<const float4*>(xb + r * DK + k);
                acc[r] = fmaf(xv.x, w0, acc[r]);
                acc[r] = fmaf(xv.y, w1, acc[r]);
                acc[r] = fmaf(xv.z, w2, acc[r]);
                acc[r] = fmaf(xv.w, w3, acc[r]);
            }
        }
        #pragma unroll
        for (int r = 0; r < 8; r++) {
            int gr = row0 + rh * 8 + r;
            if (gr < NQ) g_g[gr * DK + j] = acc[r];
        }
    } else {
        // ---- BF role: build f_W bf16 hi/lo B-fragments in m16n8k16 layout --
        // g_bf[kt4][ntg][lane]: kt4 0-7 = hi(f_W), 8-15 = lo(f_W). Each u64 =
        // (b0, b1) for mma with k-tile kt4&7, n-tile ntg (8 j), thread lane.
        int idx = (bid - EA_BLOCKS - WT_BLOCKS - PG_BLOCKS) * 256 + tid; // 0..8191
        int kt4  = idx >> 9;
        int ntg  = (idx >> 5) & 15;
        int lane = idx & 31;
        int tg = lane & 3, gid = lane >> 2;
        int n  = ntg * 8 + gid;
        int kb = (kt4 & 7) * 16 + tg * 2;
        bool ishi = (kt4 < 8);
        u32 v[4];
        #pragma unroll
        for (int r = 0; r < 4; r++) {
            int k = kb + (r & 1) + ((r >> 1) * 8);   // k0,k0+1,k0+8,k0+9
            float w = __ldg(f_W + k * DK + n);
            __nv_bfloat16 h = __float2bfloat16(w);
            float hf = __bfloat162float(h);
            __nv_bfloat16 outv = ishi ? h : __float2bfloat16(w - hf);
            v[r] = (u32)*reinterpret_cast<unsigned short*>(&outv);
        }
        u32 b0 = v[0] | (v[1] << 16);
        u32 b1 = v[2] | (v[3] << 16);
        g_bf[idx] = (u64)b0 | ((u64)b1 << 32);
    }
}

// ---------------- sequential scan (round-9 version, byte-exact) ------------
__device__ __forceinline__ void scan_loadW(int s, u64 W2[16]) {
    const ulonglong2* wp = reinterpret_cast<const ulonglong2*>(g_wt + s * CC);
    #pragma unroll
    for (int u = 0; u < 8; u++) {
        ulonglong2 v = __ldg(wp + u);
        W2[2 * u]     = v.x;
        W2[2 * u + 1] = v.y;
    }
}

__device__ __forceinline__ float scan_step(u64 m2[16], const u64 W2[16],
                                           float ne, float a) {
    u64 en2 = pack2(ne, ne);
    u64 a2  = pack2(a, a);
    u64 acc0 = 0ull, acc1 = 0ull;
    #pragma unroll
    for (int p = 0; p < 16; p++) {
        u64 mo = m2[p];
        if (p & 1) acc1 = fma2(W2[p], mo, acc1);
        else       acc0 = fma2(W2[p], mo, acc0);
        u64 tmp = fma2(mo, en2, a2);          // a - e*m
        m2[p] = fma2(W2[p], tmp, mo);         // m + w*(a - e*m)
    }
    float x0, x1, y0, y1;
    unpack2(acc0, x0, x1);
    unpack2(acc1, y0, y1);
    return (x0 + x1) + (y0 + y1);
}

__global__ void __launch_bounds__(128, 1)
scan_kernel(const int* __restrict__ skills,
            const int* __restrict__ responses,
            const float* __restrict__ Mv0) {
    int tid  = threadIdx.x;
    int half = tid >> 6;                 // 0/1 -> batch within block
    int td   = tid & 63;
    int b    = blockIdx.x * 2 + half;
    int d0   = td;
    int d1   = td + 64;

    u64 m0[16], m1[16];
    #pragma unroll
    for (int p = 0; p < 16; p++) {
        m0[p] = pack2(__ldg(Mv0 + (2 * p) * DV + d0),
                      __ldg(Mv0 + (2 * p + 1) * DV + d0));
        m1[p] = pack2(__ldg(Mv0 + (2 * p) * DV + d1),
                      __ldg(Mv0 + (2 * p + 1) * DV + d1));
    }

    const int* srow = skills + b * T;
    const int* rrow = responses + b * T;
    float* rtp0 = g_rt + (b * TOUT) * DV + d0;
    float* rtp1 = g_rt + (b * TOUT) * DV + d1;

    int    sE[8];
    float2 E0[8], E1[8];
    #pragma unroll
    for (int k = 0; k < 8; k++) {
        int s = __ldg(srow + k);
        int q = s + NQ * __ldg(rrow + k);
        sE[k] = s;
        E0[k] = __ldg(g_ea + q * DV + d0);
        E1[k] = __ldg(g_ea + q * DV + d1);
    }
    int sCur = __ldg(srow + 8);
    int qCur = sCur + NQ * __ldg(rrow + 8);

    u64 WA[16], WB[16];
    scan_loadW(sE[0], WA);

#define SCAN_BODY_STEP(k, Wc, Wn)                                          \
    {                                                                      \
        scan_loadW(sE[((k) + 1) & 7], Wn);                                 \
        rtp0[(t + (k)) * DV] = scan_step(m0, Wc, E0[k].x, E0[k].y);        \
        rtp1[(t + (k)) * DV] = scan_step(m1, Wc, E1[k].x, E1[k].y);        \
        E0[k] = __ldg(g_ea + qCur * DV + d0);                              \
        E1[k] = __ldg(g_ea + qCur * DV + d1);                              \
        sE[k] = sCur;                                                      \
        int ni = t + 9 + (k); if (ni > T - 1) ni = T - 1;                  \
        sCur = __ldg(srow + ni);                                           \
        qCur = sCur + NQ * __ldg(rrow + ni);                               \
    }

    for (int t = 0; t < 248; t += 8) {
        SCAN_BODY_STEP(0, WA, WB)
        SCAN_BODY_STEP(1, WB, WA)
        SCAN_BODY_STEP(2, WA, WB)
        SCAN_BODY_STEP(3, WB, WA)
        SCAN_BODY_STEP(4, WA, WB)
        SCAN_BODY_STEP(5, WB, WA)
        SCAN_BODY_STEP(6, WA, WB)
        SCAN_BODY_STEP(7, WB, WA)
    }
#undef SCAN_BODY_STEP

    {
        const int t = 248;
#define SCAN_TAIL_STEP(k, Wc, Wn)                                          \
        {                                                                  \
            scan_loadW(sE[(k) + 1], Wn);                                   \
            rtp0[(t + (k)) * DV] = scan_step(m0, Wc, E0[k].x, E0[k].y);    \
            rtp1[(t + (k)) * DV] = scan_step(m1, Wc, E1[k].x, E1[k].y);    \
        }
        SCAN_TAIL_STEP(0, WA, WB)
        SCAN_TAIL_STEP(1, WB, WA)
        SCAN_TAIL_STEP(2, WA, WB)
        SCAN_TAIL_STEP(3, WB, WA)
        SCAN_TAIL_STEP(4, WA, WB)
        SCAN_TAIL_STEP(5, WB, WA)
        rtp0[254 * DV] = scan_step(m0, WA, E0[6].x, E0[6].y);
        rtp1[254 * DV] = scan_step(m1, WA, E1[6].x, E1[6].y);
#undef SCAN_TAIL_STEP
    }
}

// ---------------- readout via mma.sync (bf16 3-product split) --------------
// D[64 rows x 128 j] per block. 8 warps: wm = wid&3 (16-row strip),
// wn = wid>>2 (64-j half). 24 k-tiles: kt 0-7 xhi*whi, 8-15 xlo*whi,
// 16-23 xhi*wlo (xlo*wlo dropped, ~2^-16 rel). B pre-packed in g_bf.
#define XPAD 132

__device__ __forceinline__ void mma16816(float c[4], const u32 a[4],
                                         u32 b0, u32 b1) {
    asm volatile(
        "mma.sync.aligned.m16n8k16.row.col.f32.bf16.bf16.f32 "
        "{%0,%1,%2,%3}, {%4,%5,%6,%7}, {%8,%9}, {%0,%1,%2,%3};"
        : "+f"(c[0]), "+f"(c[1]), "+f"(c[2]), "+f"(c[3])
        : "r"(a[0]), "r"(a[1]), "r"(a[2]), "r"(a[3]), "r"(b0), "r"(b1));
}

__global__ void __launch_bounds__(256)
readout_kernel(const float* __restrict__ p_W,
               const float* __restrict__ p_b,
               const int* __restrict__ skills,
               const int* __restrict__ responses,
               float* __restrict__ out,
               float* __restrict__ out2) {
    __shared__ __align__(16) float xs[64 * XPAD];
    __shared__ float red[64][2];

    int tid  = threadIdx.x;
    int lane = tid & 31;
    int wid  = tid >> 5;
    int wm   = wid & 3;
    int wn   = wid >> 2;
    int tg   = lane & 3;
    int gid  = lane >> 2;
    int row0 = blockIdx.x * 64;

    // stage X tile (64 x 128 fp32) with pad
    {
        const float4* src = reinterpret_cast<const float4*>(g_rt + row0 * DK);
        #pragma unroll
        for (int u = 0; u < 8; u++) {
            int fidx = tid + u * 256;          // 2048 float4
            int r = fidx >> 5, c4 = fidx & 31;
            *reinterpret_cast<float4*>(xs + r * XPAD + c4 * 4) = __ldg(src + fidx);
        }
    }
    __syncthreads();

    const float* xlo_row = xs + (wm * 16 + gid) * XPAD;
    const float* xhi_row = xlo_row + 8 * XPAD;

    float acc[8][4];
    #pragma unroll
    for (int nt = 0; nt < 8; nt++)
        #pragma unroll
        for (int e = 0; e < 4; e++) acc[nt][e] = 0.f;

    u32 AH[8][4];
    const u64* bbase = g_bf + (wn * 8) * 32 + lane;

    #pragma unroll
    for (int kt = 0; kt < 24; kt++) {
        u32 a[4];
        int kc = (kt & 7) * 16 + tg * 2;
        if (kt < 8) {
            float2 x0 = *reinterpret_cast<const float2*>(xlo_row + kc);
            float2 x1 = *reinterpret_cast<const float2*>(xhi_row + kc);
            float2 x2 = *reinterpret_cast<const float2*>(xlo_row + kc + 8);
            float2 x3 = *reinterpret_cast<const float2*>(xhi_row + kc + 8);
            a[0] = bfpack(x0.x, x0.y);
            a[1] = bfpack(x1.x, x1.y);
            a[2] = bfpack(x2.x, x2.y);
            a[3] = bfpack(x3.x, x3.y);
            #pragma unroll
            for (int r = 0; r < 4; r++) AH[kt][r] = a[r];
        } else if (kt < 16) {
            float2 xv[4];
            xv[0] = *reinterpret_cast<const float2*>(xlo_row + kc);
            xv[1] = *reinterpret_cast<const float2*>(xhi_row + kc);
            xv[2] = *reinterpret_cast<const float2*>(xlo_row + kc + 8);
            xv[3] = *reinterpret_cast<const float2*>(xhi_row + kc + 8);
            #pragma unroll
            for (int r = 0; r < 4; r++) {
                u32 h = AH[kt - 8][r];
                float h0 = __uint_as_float(h << 16);
                float h1 = __uint_as_float(h & 0xFFFF0000u);
                a[r] = bfpack(xv[r].x - h0, xv[r].y - h1);
            }
        } else {
            #pragma unroll
            for (int r = 0; r < 4; r++) a[r] = AH[kt - 16][r];
        }
        int bkt = (kt >= 16) ? (8 + (kt & 7)) : (kt & 7);
        const u64* bp = bbase + (bkt << 9);
        #pragma unroll
        for (int nt = 0; nt < 8; nt++) {
            u64 bv = __ldg(bp + nt * 32);
            mma16816(acc[nt], a, (u32)bv, (u32)(bv >> 32));
        }
    }

    // epilogue: + g gather, tanh, dot p_W, reduce
    int r_lo = row0 + wm * 16 + gid;
    int r_hi = r_lo + 8;
    int bb_lo = r_lo / TOUT, tt_lo = r_lo - bb_lo * TOUT;
    int bb_hi = r_hi / TOUT, tt_hi = r_hi - bb_hi * TOUT;
    int sk_lo = __ldg(skills + bb_lo * T + tt_lo);
    int sk_hi = __ldg(skills + bb_hi * T + tt_hi);

    float s_lo = 0.f, s_hi = 0.f;
    #pragma unroll
    for (int nt = 0; nt < 8; nt++) {
        int jg = wn * 64 + nt * 8 + tg * 2;
        float2 pw  = __ldg(reinterpret_cast<const float2*>(p_W + jg));
        float2 glo = __ldg(reinterpret_cast<const float2*>(g_g + sk_lo * DK + jg));
        float2 ghi = __ldg(reinterpret_cast<const float2*>(g_g + sk_hi * DK + jg));
        s_lo = fmaf(tanhf(acc[nt][0] + glo.x), pw.x, s_lo);
        s_lo = fmaf(tanhf(acc[nt][1] + glo.y), pw.y, s_lo);
        s_hi = fmaf(tanhf(acc[nt][2] + ghi.x), pw.x, s_hi);
        s_hi = fmaf(tanhf(acc[nt][3] + ghi.y), pw.y, s_hi);
    }
    s_lo += __shfl_xor_sync(0xffffffffu, s_lo, 1);
    s_lo += __shfl_xor_sync(0xffffffffu, s_lo, 2);
    s_hi += __shfl_xor_sync(0xffffffffu, s_hi, 1);
    s_hi += __shfl_xor_sync(0xffffffffu, s_hi, 2);
    if (tg == 0) {
        red[wm * 16 + gid][wn]     = s_lo;
        red[wm * 16 + gid + 8][wn] = s_hi;
    }
    __syncthreads();

    if (tid < 64) {
        float s = red[tid][0] + red[tid][1] + __ldg(p_b);
        int gr = row0 + tid;
        int bb = gr / TOUT;
        int tt = gr - bb * TOUT;
        out[gr]  = 1.0f / (1.0f + expf(-s));
        out2[gr] = (float)__ldg(responses + bb * T + tt + 1);
    }
}

// ---------------- launch ----------------------------------------------------
extern "C" void kernel_launch(void* const* d_in, const int* in_sizes, int n_in,
                              void* d_out, int out_size) {
    const int*   skills    = (const int*)  d_in[0];
    const int*   responses = (const int*)  d_in[1];
    const float* k_emb     = (const float*)d_in[2];
    const float* v_emb     = (const float*)d_in[3];
    const float* Mk        = (const float*)d_in[4];
    const float* Mv0       = (const float*)d_in[5];
    const float* f_W       = (const float*)d_in[6];
    const float* f_b       = (const float*)d_in[7];
    const float* p_W       = (const float*)d_in[8];
    const float* p_b       = (const float*)d_in[9];
    const float* e_W       = (const float*)d_in[10];
    const float* e_b       = (const float*)d_in[11];
    const float* a_W       = (const float*)d_in[12];
    const float* a_b       = (const float*)d_in[13];

    float* pred_out = (float*)d_out;
    float* true_out = pred_out + (out_size / 2);

    pre_fused_kernel<<<PRE_BLOCKS, 256>>>(k_emb, v_emb, Mk, f_W, f_b,
                                          e_W, e_b, a_W, a_b);

    scan_kernel<<<B / 2, 128>>>(skills, responses, Mv0);

    readout_kernel<<<NROWS / 64, 256>>>(p_W, p_b, skills, responses,
                                        pred_out, true_out);
}